// round 9
// baseline (speedup 1.0000x reference)
#include <cuda_runtime.h>

// Problem constants
#define B_  8
#define N_  1024
#define C_  64
#define O_  64
#define KM  4          // K+1
#define BN  (B_*N_)    // 8192

// -------- device scratch --------
__device__ float g_sRi[BN], g_sIi[BN], g_sRj[BN], g_sIj[BN];
__device__ float g_rsum[BN];                   // 1 / sum_i exp(mag) per (b,j)
__device__ float g_row[BN*8];                  // [bn][0..3]=rowR[m], [4..7]=rowI[m]
__device__ float g_PR[BN*KM*O_], g_PI[BN*KM*O_]; // [bn][m][o]

// ============================================================
// Kernel 1: per-(b,n) attention projections. One warp per (b,n).
// ============================================================
__global__ void __launch_bounds__(256) k1_proj(
    const float* __restrict__ Xr, const float* __restrict__ Xi,
    const float* __restrict__ awr, const float* __restrict__ awi,
    const float* __restrict__ abr, const float* __restrict__ abi)
{
    int warp = (blockIdx.x * blockDim.x + threadIdx.x) >> 5;
    int lane = threadIdx.x & 31;
    if (warp >= BN) return;
    const float* xr = Xr + warp * C_;
    const float* xi = Xi + warp * C_;
    float sRi = 0.f, sIi = 0.f, sRj = 0.f, sIj = 0.f;
#pragma unroll
    for (int t = 0; t < 2; t++) {
        int c = lane + t * 32;
        float a = xr[c], b = xi[c];
        float wri = awr[c],      wii = awi[c];
        float wrj = awr[C_ + c], wij = awi[C_ + c];
        sRi += a * wri - b * wii;
        sIi += a * wii + b * wri;
        sRj += a * wrj - b * wij;
        sIj += a * wij + b * wrj;
    }
#pragma unroll
    for (int off = 16; off; off >>= 1) {
        sRi += __shfl_xor_sync(0xffffffffu, sRi, off);
        sIi += __shfl_xor_sync(0xffffffffu, sIi, off);
        sRj += __shfl_xor_sync(0xffffffffu, sRj, off);
        sIj += __shfl_xor_sync(0xffffffffu, sIj, off);
    }
    if (lane == 0) {
        g_sRi[warp] = sRi + abr[0];
        g_sIi[warp] = sIi + abi[0];
        g_sRj[warp] = sRj;
        g_sIj[warp] = sIj;
    }
}

// ============================================================
// Kernel 2: softmax denominator per (b,j): sum over i of exp(mag).
// ============================================================
__global__ void __launch_bounds__(128) k2_sumexp(
    const float* __restrict__ par, const float* __restrict__ pai)
{
    int bj = blockIdx.x;          // b*N + j
    int b  = bj >> 10;
    float sRj = g_sRj[bj], sIj = g_sIj[bj];
    float a_r = par[0], a_i = pai[0];
    const float* sRi = g_sRi + (b << 10);
    const float* sIi = g_sIi + (b << 10);
    float acc = 0.f;
#pragma unroll
    for (int t = 0; t < N_ / 128; t++) {
        int i = threadIdx.x + t * 128;
        float sr = sRi[i] + sRj;
        float si = sIi[i] + sIj;
        float pr = sr >= 0.f ? sr : a_r * sr;
        float pi = si >= 0.f ? si : a_i * si;
        float r2 = pr * pr + pi * pi;
        float inv = rsqrtf(fmaxf(r2, 1e-30f));
        float mag = r2 * inv;
        acc += __expf(mag);
    }
    __shared__ float sred[4];
#pragma unroll
    for (int off = 16; off; off >>= 1) acc += __shfl_xor_sync(0xffffffffu, acc, off);
    if ((threadIdx.x & 31) == 0) sred[threadIdx.x >> 5] = acc;
    __syncthreads();
    if (threadIdx.x == 0) {
        float t = sred[0] + sred[1] + sred[2] + sred[3];
        g_rsum[bj] = 1.f / t;
    }
}

// ============================================================
// Fused k34: role-specialized blocks interleaved by bid%3.
//   bid%3==0 (256 blocks): k3-role — stream L (DRAM), warp-per-row,
//     loads issued FIRST each chunk for MLP, MUFU overlapped.
//   else     (512 blocks): k4a-role — P compute (FMA), to scratch.
// ============================================================
#define FMA4(acc, s, v) \
    acc.x += (s) * (v).x; acc.y += (s) * (v).y; \
    acc.z += (s) * (v).z; acc.w += (s) * (v).w;

#define XSW(j, q) (((j) << 2) | ((q) ^ ((j) & 3) ^ (((j) >> 2) & 3)))

__global__ void __launch_bounds__(128, 4) k34(
    const float* __restrict__ Xr, const float* __restrict__ Xi,
    const float* __restrict__ Lr, const float* __restrict__ Li,
    const float4* __restrict__ wr4, const float4* __restrict__ wi4,
    const float* __restrict__ par, const float* __restrict__ pai)
{
    __shared__ float4 wr_s[KM * C_ * 4];     // 16 KB (k4a); k3 reuses as scratch
    __shared__ float4 wi_s[KM * C_ * 4];     // 16 KB
    __shared__ float4 x_s[2][2][256];        // 16 KB

    const int bx  = blockIdx.x;
    const int tid = threadIdx.x;

    if (bx % 3 == 0) {
        // ================= k3-role =================
        const int kid   = bx / 3;            // 0..255
        const int b     = kid >> 5;
        const int ibase = (kid & 31) << 5;   // 32 rows per block
        const int warp  = tid >> 5;
        const int lane  = tid & 31;
        const float a_r = par[0], a_i = pai[0];

#pragma unroll 1
        for (int rr = 0; rr < 8; rr++) {
            int ig = ibase + warp * 8 + rr;
            float sRiv = g_sRi[(b << 10) + ig];
            float sIiv = g_sIi[(b << 10) + ig];
            float accR[4] = {0.f,0.f,0.f,0.f};
            float accI[4] = {0.f,0.f,0.f,0.f};
#pragma unroll 1
            for (int ch = 0; ch < 8; ch++) {
                int j0  = ch * 128 + lane * 4;
                // ---- L loads FIRST (8 independent LDG.128, MLP) ----
                float4 lr0, lr1, lr2, lr3, li0, li1, li2, li3;
                {
                    size_t b0 = (((size_t)((b << 2) + 0) << 10) + ig) << 10;
                    size_t b1 = (((size_t)((b << 2) + 1) << 10) + ig) << 10;
                    size_t b2 = (((size_t)((b << 2) + 2) << 10) + ig) << 10;
                    size_t b3 = (((size_t)((b << 2) + 3) << 10) + ig) << 10;
                    lr0 = *(const float4*)(Lr + b0 + j0);
                    lr1 = *(const float4*)(Lr + b1 + j0);
                    lr2 = *(const float4*)(Lr + b2 + j0);
                    lr3 = *(const float4*)(Lr + b3 + j0);
                    li0 = *(const float4*)(Li + b0 + j0);
                    li1 = *(const float4*)(Li + b1 + j0);
                    li2 = *(const float4*)(Li + b2 + j0);
                    li3 = *(const float4*)(Li + b3 + j0);
                }
                // ---- ar/ai (s loads are L1/L2-hot; MUFU overlaps L flight) ----
                int bj0 = (b << 10) + j0;
                float4 sRj4 = *(const float4*)(g_sRj + bj0);
                float4 sIj4 = *(const float4*)(g_sIj + bj0);
                float4 rs4  = *(const float4*)(g_rsum + bj0);
                const float* srj = (const float*)&sRj4;
                const float* sij = (const float*)&sIj4;
                const float* rsv = (const float*)&rs4;
                float ar[4], ai[4];
#pragma unroll
                for (int k = 0; k < 4; k++) {
                    float sr = sRiv + srj[k];
                    float si = sIiv + sij[k];
                    float pr = sr >= 0.f ? sr : a_r * sr;
                    float pi = si >= 0.f ? si : a_i * si;
                    float r2 = pr * pr + pi * pi;
                    float inv = rsqrtf(fmaxf(r2, 1e-30f));
                    float e = __expf(r2 * inv);
                    float sc = e * inv * rsv[k];
                    ar[k] = sc * pr;
                    ai[k] = sc * pi;
                }
                // ---- accumulate ----
                accR[0] += lr0.x*ar[0] - li0.x*ai[0];  accI[0] += lr0.x*ai[0] + li0.x*ar[0];
                accR[0] += lr0.y*ar[1] - li0.y*ai[1];  accI[0] += lr0.y*ai[1] + li0.y*ar[1];
                accR[0] += lr0.z*ar[2] - li0.z*ai[2];  accI[0] += lr0.z*ai[2] + li0.z*ar[2];
                accR[0] += lr0.w*ar[3] - li0.w*ai[3];  accI[0] += lr0.w*ai[3] + li0.w*ar[3];
                accR[1] += lr1.x*ar[0] - li1.x*ai[0];  accI[1] += lr1.x*ai[0] + li1.x*ar[0];
                accR[1] += lr1.y*ar[1] - li1.y*ai[1];  accI[1] += lr1.y*ai[1] + li1.y*ar[1];
                accR[1] += lr1.z*ar[2] - li1.z*ai[2];  accI[1] += lr1.z*ai[2] + li1.z*ar[2];
                accR[1] += lr1.w*ar[3] - li1.w*ai[3];  accI[1] += lr1.w*ai[3] + li1.w*ar[3];
                accR[2] += lr2.x*ar[0] - li2.x*ai[0];  accI[2] += lr2.x*ai[0] + li2.x*ar[0];
                accR[2] += lr2.y*ar[1] - li2.y*ai[1];  accI[2] += lr2.y*ai[1] + li2.y*ar[1];
                accR[2] += lr2.z*ar[2] - li2.z*ai[2];  accI[2] += lr2.z*ai[2] + li2.z*ar[2];
                accR[2] += lr2.w*ar[3] - li2.w*ai[3];  accI[2] += lr2.w*ai[3] + li2.w*ar[3];
                accR[3] += lr3.x*ar[0] - li3.x*ai[0];  accI[3] += lr3.x*ai[0] + li3.x*ar[0];
                accR[3] += lr3.y*ar[1] - li3.y*ai[1];  accI[3] += lr3.y*ai[1] + li3.y*ar[1];
                accR[3] += lr3.z*ar[2] - li3.z*ai[2];  accI[3] += lr3.z*ai[2] + li3.z*ar[2];
                accR[3] += lr3.w*ar[3] - li3.w*ai[3];  accI[3] += lr3.w*ai[3] + li3.w*ar[3];
            }
            // warp-reduce 8 values, lane0 writes interleaved layout
#pragma unroll
            for (int q = 0; q < 8; q++) {
                float x = (q < 4) ? accR[q] : accI[q - 4];
#pragma unroll
                for (int off = 16; off; off >>= 1)
                    x += __shfl_xor_sync(0xffffffffu, x, off);
                if (lane == 0)
                    g_row[(((b << 10) + ig) << 3) + q] = x;
            }
        }
        return;
    }

    // ================= k4a-role =================
    const int t4  = bx - bx / 3 - 1;         // 0..511
    const int og  = tid & 3;
    const int jl  = tid >> 2;                // 0..31
    const int jg  = t4 & 127;
    const int oq  = t4 >> 7;                 // 0..3
    const int jbase = jg * 64;

    const float4* XrG = (const float4*)Xr + (size_t)jbase * 16;
    const float4* XiG = (const float4*)Xi + (size_t)jbase * 16;

#pragma unroll
    for (int r = 0; r < 8; r++) {
        int e  = r * 128 + tid;
        int mc = e >> 2, o2 = e & 3;
        wr_s[e] = wr4[mc * 16 + oq * 4 + o2];
        wi_s[e] = wi4[mc * 16 + oq * 4 + o2];
    }
#pragma unroll
    for (int r = 0; r < 2; r++) {
        int e = r * 128 + tid;
        int j = e >> 2, q = e & 3;
        int si = XSW(j, q);
        x_s[0][0][si] = XrG[j * 16 + q];
        x_s[0][1][si] = XiG[j * 16 + q];
    }
    __syncthreads();

    float4 PR0[4], PI0[4], PR1[4], PI1[4];
#pragma unroll
    for (int m = 0; m < 4; m++) {
        PR0[m] = make_float4(0.f,0.f,0.f,0.f); PI0[m] = make_float4(0.f,0.f,0.f,0.f);
        PR1[m] = make_float4(0.f,0.f,0.f,0.f); PI1[m] = make_float4(0.f,0.f,0.f,0.f);
    }
    const int j0 = jl, j1 = jl + 32;

#pragma unroll
    for (int p = 0; p < 4; p++) {
        int buf = p & 1;
        if (p < 3) {
            int nb = buf ^ 1;
#pragma unroll
            for (int r = 0; r < 2; r++) {
                int e = r * 128 + tid;
                int j = e >> 2, q = e & 3;
                int si = XSW(j, q);
                x_s[nb][0][si] = XrG[j * 16 + (p + 1) * 4 + q];
                x_s[nb][1][si] = XiG[j * 16 + (p + 1) * 4 + q];
            }
        }
#pragma unroll
        for (int q = 0; q < 4; q++) {
            float4 xr0 = x_s[buf][0][XSW(j0, q)];
            float4 xi0 = x_s[buf][1][XSW(j0, q)];
            float4 xr1 = x_s[buf][0][XSW(j1, q)];
            float4 xi1 = x_s[buf][1][XSW(j1, q)];
            const float* fxr0 = (const float*)&xr0;
            const float* fxi0 = (const float*)&xi0;
            const float* fxr1 = (const float*)&xr1;
            const float* fxi1 = (const float*)&xi1;
#pragma unroll
            for (int ci = 0; ci < 4; ci++) {
                int c = p * 16 + q * 4 + ci;
                float a0 = fxr0[ci], b0 = fxi0[ci];
                float a1 = fxr1[ci], b1 = fxi1[ci];
#pragma unroll
                for (int m = 0; m < 4; m++) {
                    float4 wr = wr_s[((m << 6) + c) * 4 + og];
                    float4 wi = wi_s[((m << 6) + c) * 4 + og];
                    FMA4(PR0[m], a0, wr);
                    FMA4(PI0[m], b0, wi);
                    FMA4(PR1[m], a1, wr);
                    FMA4(PI1[m], b1, wi);
                }
            }
        }
        __syncthreads();
    }

    float4* PR4 = (float4*)g_PR;
    float4* PI4 = (float4*)g_PI;
#pragma unroll
    for (int jt = 0; jt < 2; jt++) {
        int jj = jbase + jl + jt * 32;
        size_t base = (size_t)jj * 64 + oq * 4 + og;
#pragma unroll
        for (int m = 0; m < 4; m++) {
            PR4[base + m * 16] = jt ? PR1[m] : PR0[m];
            PI4[base + m * 16] = jt ? PI1[m] : PI0[m];
        }
    }
}

// ============================================================
// k4b: combine. Thread = (bn, og). row vectors now float4-loadable.
// ============================================================
__global__ void __launch_bounds__(128) k4b_combine(float* __restrict__ out)
{
    int gid = blockIdx.x * 128 + threadIdx.x;    // bn*16 + og
    int bn  = gid >> 4;
    int og  = gid & 15;

    const float4* PR4 = (const float4*)g_PR;
    const float4* PI4 = (const float4*)g_PI;
    size_t base = (size_t)bn * 64 + og;

    // issue all P loads first (MLP 8)
    float4 pr0 = PR4[base];      float4 pr1 = PR4[base + 16];
    float4 pr2 = PR4[base + 32]; float4 pr3 = PR4[base + 48];
    float4 pi0 = PI4[base];      float4 pi1 = PI4[base + 16];
    float4 pi2 = PI4[base + 32]; float4 pi3 = PI4[base + 48];

    const float4* row4 = (const float4*)g_row;
    float4 rR = row4[bn * 2];
    float4 rI = row4[bn * 2 + 1];
    const float* aR = (const float*)&rR;
    const float* aI = (const float*)&rI;

    float4 re = make_float4(0.f,0.f,0.f,0.f);
    float4 im = make_float4(0.f,0.f,0.f,0.f);
    const float4 prv[4] = {pr0, pr1, pr2, pr3};
    const float4 piv[4] = {pi0, pi1, pi2, pi3};
#pragma unroll
    for (int m = 0; m < 4; m++) {
        float a  = aR[m];
        float bi = aI[m];
        re.x += a * prv[m].x - bi * piv[m].x;  re.y += a * prv[m].y - bi * piv[m].y;
        re.z += a * prv[m].z - bi * piv[m].z;  re.w += a * prv[m].w - bi * piv[m].w;
        im.x += bi * prv[m].x + a * piv[m].x;  im.y += bi * prv[m].y + a * piv[m].y;
        im.z += bi * prv[m].z + a * piv[m].z;  im.w += bi * prv[m].w + a * piv[m].w;
    }
    float4* o4 = (float4*)out;
    o4[(size_t)bn * 16 + og] = re;
    o4[(size_t)BN * 16 + (size_t)bn * 16 + og] = im;
}

// ============================================================
extern "C" void kernel_launch(void* const* d_in, const int* in_sizes, int n_in,
                              void* d_out, int out_size)
{
    const float* Xr  = (const float*)d_in[0];
    const float* Xi  = (const float*)d_in[1];
    const float* Lr  = (const float*)d_in[2];
    const float* Li  = (const float*)d_in[3];
    const float* wr  = (const float*)d_in[4];
    const float* wi  = (const float*)d_in[5];
    const float* awr = (const float*)d_in[6];
    const float* awi = (const float*)d_in[7];
    const float* abr = (const float*)d_in[8];
    const float* abi = (const float*)d_in[9];
    const float* par = (const float*)d_in[10];
    const float* pai = (const float*)d_in[11];
    float* out = (float*)d_out;

    k1_proj    <<<BN / 8, 256>>>(Xr, Xi, awr, awi, abr, abi);
    k2_sumexp  <<<BN,     128>>>(par, pai);
    k34        <<<768,    128>>>(Xr, Xi, Lr, Li,
                                 (const float4*)wr, (const float4*)wi,
                                 par, pai);
    k4b_combine<<<BN * 16 / 128, 128>>>(out);
}

// round 10
// speedup vs baseline: 1.1982x; 1.1982x over previous
#include <cuda_runtime.h>

// Problem constants
#define B_  8
#define N_  1024
#define C_  64
#define O_  64
#define KM  4          // K+1
#define BN  (B_*N_)    // 8192

// -------- device scratch --------
__device__ float g_sRi[BN], g_sIi[BN], g_sRj[BN], g_sIj[BN];
__device__ float g_rsum[BN];     // 1 / sum_i exp(mag) per (b,j)
__device__ float g_row[BN*8];    // [bn][0..3]=rowR[m], [4..7]=rowI[m]

// ============================================================
// Kernel 1: per-(b,n) attention projections. One warp per (b,n).
// ============================================================
__global__ void __launch_bounds__(256) k1_proj(
    const float* __restrict__ Xr, const float* __restrict__ Xi,
    const float* __restrict__ awr, const float* __restrict__ awi,
    const float* __restrict__ abr, const float* __restrict__ abi)
{
    int warp = (blockIdx.x * blockDim.x + threadIdx.x) >> 5;
    int lane = threadIdx.x & 31;
    if (warp >= BN) return;
    const float* xr = Xr + warp * C_;
    const float* xi = Xi + warp * C_;
    float sRi = 0.f, sIi = 0.f, sRj = 0.f, sIj = 0.f;
#pragma unroll
    for (int t = 0; t < 2; t++) {
        int c = lane + t * 32;
        float a = xr[c], b = xi[c];
        float wri = awr[c],      wii = awi[c];
        float wrj = awr[C_ + c], wij = awi[C_ + c];
        sRi += a * wri - b * wii;
        sIi += a * wii + b * wri;
        sRj += a * wrj - b * wij;
        sIj += a * wij + b * wrj;
    }
#pragma unroll
    for (int off = 16; off; off >>= 1) {
        sRi += __shfl_xor_sync(0xffffffffu, sRi, off);
        sIi += __shfl_xor_sync(0xffffffffu, sIi, off);
        sRj += __shfl_xor_sync(0xffffffffu, sRj, off);
        sIj += __shfl_xor_sync(0xffffffffu, sIj, off);
    }
    if (lane == 0) {
        g_sRi[warp] = sRi + abr[0];
        g_sIi[warp] = sIi + abi[0];
        g_sRj[warp] = sRj;
        g_sIj[warp] = sIj;
    }
}

// ============================================================
// Kernel 2: softmax denominator per (b,j): sum over i of exp(mag).
// ============================================================
__global__ void __launch_bounds__(128) k2_sumexp(
    const float* __restrict__ par, const float* __restrict__ pai)
{
    int bj = blockIdx.x;          // b*N + j
    int b  = bj >> 10;
    float sRj = g_sRj[bj], sIj = g_sIj[bj];
    float a_r = par[0], a_i = pai[0];
    const float* sRi = g_sRi + (b << 10);
    const float* sIi = g_sIi + (b << 10);
    float acc = 0.f;
#pragma unroll
    for (int t = 0; t < N_ / 128; t++) {
        int i = threadIdx.x + t * 128;
        float sr = sRi[i] + sRj;
        float si = sIi[i] + sIj;
        float pr = sr >= 0.f ? sr : a_r * sr;
        float pi = si >= 0.f ? si : a_i * si;
        float r2 = pr * pr + pi * pi;
        float inv = rsqrtf(fmaxf(r2, 1e-30f));
        float mag = r2 * inv;
        acc += __expf(mag);
    }
    __shared__ float sred[4];
#pragma unroll
    for (int off = 16; off; off >>= 1) acc += __shfl_xor_sync(0xffffffffu, acc, off);
    if ((threadIdx.x & 31) == 0) sred[threadIdx.x >> 5] = acc;
    __syncthreads();
    if (threadIdx.x == 0) {
        float t = sred[0] + sred[1] + sred[2] + sred[3];
        g_rsum[bj] = 1.f / t;
    }
}

// ============================================================
// Kernel 3 (HBM-bound): one block per (b,i) row.
// Streams L_real/L_imag exactly once (268 MB) -> g_row (interleaved).
// ============================================================
__global__ void __launch_bounds__(256) k3_main(
    const float* __restrict__ Lr, const float* __restrict__ Li,
    const float* __restrict__ par, const float* __restrict__ pai)
{
    int bi = blockIdx.x;          // b*N + i
    int b  = bi >> 10;
    int i  = bi & 1023;
    int tid = threadIdx.x;
    int j0 = tid * 4;

    float sRi = g_sRi[bi], sIi = g_sIi[bi];
    float a_r = par[0], a_i = pai[0];

    const int bj0 = (b << 10) + j0;
    float4 sRj4 = *(const float4*)(g_sRj + bj0);
    float4 sIj4 = *(const float4*)(g_sIj + bj0);
    float4 rs4  = *(const float4*)(g_rsum + bj0);
    float sRjv[4] = {sRj4.x, sRj4.y, sRj4.z, sRj4.w};
    float sIjv[4] = {sIj4.x, sIj4.y, sIj4.z, sIj4.w};
    float rsv [4] = {rs4.x,  rs4.y,  rs4.z,  rs4.w };

    float ar[4], ai[4];
#pragma unroll
    for (int k = 0; k < 4; k++) {
        float sr = sRi + sRjv[k];
        float si = sIi + sIjv[k];
        float pr = sr >= 0.f ? sr : a_r * sr;
        float pi = si >= 0.f ? si : a_i * si;
        float r2 = pr * pr + pi * pi;
        float inv = rsqrtf(fmaxf(r2, 1e-30f));
        float mag = r2 * inv;
        float e = __expf(mag);
        float sc = e * inv * rsv[k];
        ar[k] = sc * pr;
        ai[k] = sc * pi;
    }

    float accR[4], accI[4];
#pragma unroll
    for (int m = 0; m < 4; m++) { accR[m] = 0.f; accI[m] = 0.f; }

#pragma unroll
    for (int m = 0; m < 4; m++) {
        size_t base = ((size_t)((b * 4 + m) * N_ + i)) * N_ + j0;
        float4 lr = *(const float4*)(Lr + base);
        float4 li = *(const float4*)(Li + base);
        accR[m] += lr.x * ar[0] - li.x * ai[0];
        accR[m] += lr.y * ar[1] - li.y * ai[1];
        accR[m] += lr.z * ar[2] - li.z * ai[2];
        accR[m] += lr.w * ar[3] - li.w * ai[3];
        accI[m] += lr.x * ai[0] + li.x * ar[0];
        accI[m] += lr.y * ai[1] + li.y * ar[1];
        accI[m] += lr.z * ai[2] + li.z * ar[2];
        accI[m] += lr.w * ai[3] + li.w * ar[3];
    }

    __shared__ float sred[8][8];   // [warp][q]
#pragma unroll
    for (int q = 0; q < 8; q++) {
        float x = (q < 4) ? accR[q] : accI[q - 4];
#pragma unroll
        for (int off = 16; off; off >>= 1) x += __shfl_xor_sync(0xffffffffu, x, off);
        if ((tid & 31) == 0) sred[tid >> 5][q] = x;
    }
    __syncthreads();
    if (tid < 8) {
        float x = 0.f;
#pragma unroll
        for (int w = 0; w < 8; w++) x += sred[w][tid];
        g_row[(bi << 3) + tid] = x;    // [bn][0..3]=R, [4..7]=I
    }
}

// ============================================================
// Kernel 4: final einsums, broadcast-w scheme (lane = j).
// Block 128 thr = 4 warps = (jhalf, osub); covers 64 j x 8 o.
//   smem: w slice [mc][ri][2 f4]  = 16 KB
//         X tile  [ri][c][j^swz]  = 32 KB     (48 KB total, static)
// Per c per thread: 8 broadcast LDS.128 (w) + 2 LDS.32 (x) + 32 FFMA.
// Grid = 8 oq x 128 jg = 1024 blocks, 4/SM -> 16 warps/SM.
// Combine with g_row inlined; writes out directly.
// ============================================================
#define FMA4(acc, s, v) \
    acc.x += (s) * (v).x; acc.y += (s) * (v).y; \
    acc.z += (s) * (v).z; acc.w += (s) * (v).w;

__global__ void __launch_bounds__(128, 4) k4_out(
    const float* __restrict__ Xr, const float* __restrict__ Xi,
    const float4* __restrict__ wr4, const float4* __restrict__ wi4,
    float* __restrict__ out)
{
    __shared__ float4 ws4[1024];        // [mc][ {wr f4 x2} {wi f4 x2} ]
    __shared__ float  xsl[2][64][64];   // [ri][c][ j ^ (c&31) ]

    const int tid = threadIdx.x;
    const int bx  = blockIdx.x;
    const int jg  = bx & 127;
    const int oq  = bx >> 7;            // 0..7 (8-o slice)
    const int jbase = jg * 64;
    const int wid = tid >> 5;
    const int lane = tid & 31;
    const int jhalf = wid & 1;
    const int osub  = wid >> 1;         // 0..1 -> which f4 of the 8-o slice
    const int j = jhalf * 32 + lane;    // 0..63 (this thread's j within tile)

    // ---- w slice: [mc]*4 + {0,1}=wr, {2,3}=wi ----
#pragma unroll
    for (int r = 0; r < 4; r++) {
        int e  = r * 128 + tid;         // 0..511
        int mc = e >> 1, o2 = e & 1;
        ws4[mc * 4 + o2]     = wr4[mc * 16 + oq * 2 + o2];
        ws4[mc * 4 + 2 + o2] = wi4[mc * 16 + oq * 2 + o2];
    }
    // ---- X tile: coalesced f4 loads, swizzled scalar stores ----
    {
        const float4* XrG = (const float4*)Xr + (size_t)jbase * 16;
        const float4* XiG = (const float4*)Xi + (size_t)jbase * 16;
#pragma unroll
        for (int r = 0; r < 8; r++) {
            int e  = r * 128 + tid;     // 0..1023
            int jj = e >> 4, cq = e & 15;
            float4 vr = XrG[jj * 16 + cq];
            float4 vi = XiG[jj * 16 + cq];
            const float* fr = (const float*)&vr;
            const float* fi = (const float*)&vi;
#pragma unroll
            for (int ci = 0; ci < 4; ci++) {
                int c = cq * 4 + ci;
                xsl[0][c][jj ^ (c & 31)] = fr[ci];
                xsl[1][c][jj ^ (c & 31)] = fi[ci];
            }
        }
    }
    __syncthreads();

    // ---- main loop: FMA-bound, w reads are warp-broadcast ----
    float4 PR[4], PI[4];
#pragma unroll
    for (int m = 0; m < 4; m++) {
        PR[m] = make_float4(0.f,0.f,0.f,0.f);
        PI[m] = make_float4(0.f,0.f,0.f,0.f);
    }
#pragma unroll 8
    for (int c = 0; c < C_; c++) {
        float xr = xsl[0][c][j ^ (c & 31)];
        float xi = xsl[1][c][j ^ (c & 31)];
#pragma unroll
        for (int m = 0; m < 4; m++) {
            float4 wr = ws4[(m * 64 + c) * 4 + osub];
            float4 wi = ws4[(m * 64 + c) * 4 + 2 + osub];
            FMA4(PR[m], xr, wr);
            FMA4(PI[m], xi, wi);
        }
    }

    // ---- combine with row vectors and store ----
    const int bn = jbase + j;
    const float4* row4 = (const float4*)g_row;
    float4 rR = row4[bn * 2];
    float4 rI = row4[bn * 2 + 1];
    const float* aR = (const float*)&rR;
    const float* aI = (const float*)&rI;

    float4 re = make_float4(0.f,0.f,0.f,0.f);
    float4 im = make_float4(0.f,0.f,0.f,0.f);
#pragma unroll
    for (int m = 0; m < 4; m++) {
        float a  = aR[m];
        float bi = aI[m];
        re.x += a * PR[m].x - bi * PI[m].x;  re.y += a * PR[m].y - bi * PI[m].y;
        re.z += a * PR[m].z - bi * PI[m].z;  re.w += a * PR[m].w - bi * PI[m].w;
        im.x += bi * PR[m].x + a * PI[m].x;  im.y += bi * PR[m].y + a * PI[m].y;
        im.z += bi * PR[m].z + a * PI[m].z;  im.w += bi * PR[m].w + a * PI[m].w;
    }
    float4* o4 = (float4*)out;
    o4[(size_t)bn * 16 + oq * 2 + osub] = re;                      // real
    o4[(size_t)BN * 16 + (size_t)bn * 16 + oq * 2 + osub] = im;    // imag
}

// ============================================================
extern "C" void kernel_launch(void* const* d_in, const int* in_sizes, int n_in,
                              void* d_out, int out_size)
{
    const float* Xr  = (const float*)d_in[0];
    const float* Xi  = (const float*)d_in[1];
    const float* Lr  = (const float*)d_in[2];
    const float* Li  = (const float*)d_in[3];
    const float* wr  = (const float*)d_in[4];
    const float* wi  = (const float*)d_in[5];
    const float* awr = (const float*)d_in[6];
    const float* awi = (const float*)d_in[7];
    const float* abr = (const float*)d_in[8];
    const float* abi = (const float*)d_in[9];
    const float* par = (const float*)d_in[10];
    const float* pai = (const float*)d_in[11];
    float* out = (float*)d_out;

    k1_proj  <<<BN / 8, 256>>>(Xr, Xi, awr, awi, abr, abi);
    k2_sumexp<<<BN,     128>>>(par, pai);
    k3_main  <<<BN,     256>>>(Lr, Li, par, pai);
    k4_out   <<<8 * 128, 128>>>(Xr, Xi, (const float4*)wr, (const float4*)wi, out);
}

// round 12
// speedup vs baseline: 1.2337x; 1.0297x over previous
#include <cuda_runtime.h>
#include <cstdint>

// Problem constants
#define B_  8
#define N_  1024
#define C_  64
#define O_  64
#define KM  4          // K+1
#define BN  (B_*N_)    // 8192

// -------- device scratch --------
__device__ float g_sRi[BN], g_sIi[BN], g_sRj[BN], g_sIj[BN];
__device__ float g_rsum[BN];     // 1 / sum_i exp(mag) per (b,j)
__device__ float g_row[BN*8];    // [bn][0..3]=rowR[m], [4..7]=rowI[m]

// ============================================================
// Kernel 1: per-(b,n) attention projections. One warp per (b,n).
// ============================================================
__global__ void __launch_bounds__(256) k1_proj(
    const float* __restrict__ Xr, const float* __restrict__ Xi,
    const float* __restrict__ awr, const float* __restrict__ awi,
    const float* __restrict__ abr, const float* __restrict__ abi)
{
    int warp = (blockIdx.x * blockDim.x + threadIdx.x) >> 5;
    int lane = threadIdx.x & 31;
    if (warp >= BN) return;
    const float* xr = Xr + warp * C_;
    const float* xi = Xi + warp * C_;
    float sRi = 0.f, sIi = 0.f, sRj = 0.f, sIj = 0.f;
#pragma unroll
    for (int t = 0; t < 2; t++) {
        int c = lane + t * 32;
        float a = xr[c], b = xi[c];
        float wri = awr[c],      wii = awi[c];
        float wrj = awr[C_ + c], wij = awi[C_ + c];
        sRi += a * wri - b * wii;
        sIi += a * wii + b * wri;
        sRj += a * wrj - b * wij;
        sIj += a * wij + b * wrj;
    }
#pragma unroll
    for (int off = 16; off; off >>= 1) {
        sRi += __shfl_xor_sync(0xffffffffu, sRi, off);
        sIi += __shfl_xor_sync(0xffffffffu, sIi, off);
        sRj += __shfl_xor_sync(0xffffffffu, sRj, off);
        sIj += __shfl_xor_sync(0xffffffffu, sIj, off);
    }
    if (lane == 0) {
        g_sRi[warp] = sRi + abr[0];
        g_sIi[warp] = sIi + abi[0];
        g_sRj[warp] = sRj;
        g_sIj[warp] = sIj;
    }
}

// ============================================================
// Kernel 2: softmax denominator per (b,j): sum over i of exp(mag).
// ============================================================
__global__ void __launch_bounds__(128) k2_sumexp(
    const float* __restrict__ par, const float* __restrict__ pai)
{
    int bj = blockIdx.x;          // b*N + j
    int b  = bj >> 10;
    float sRj = g_sRj[bj], sIj = g_sIj[bj];
    float a_r = par[0], a_i = pai[0];
    const float* sRi = g_sRi + (b << 10);
    const float* sIi = g_sIi + (b << 10);
    float acc = 0.f;
#pragma unroll
    for (int t = 0; t < N_ / 128; t++) {
        int i = threadIdx.x + t * 128;
        float sr = sRi[i] + sRj;
        float si = sIi[i] + sIj;
        float pr = sr >= 0.f ? sr : a_r * sr;
        float pi = si >= 0.f ? si : a_i * si;
        float r2 = pr * pr + pi * pi;
        float inv = rsqrtf(fmaxf(r2, 1e-30f));
        float mag = r2 * inv;
        acc += __expf(mag);
    }
    __shared__ float sred[4];
#pragma unroll
    for (int off = 16; off; off >>= 1) acc += __shfl_xor_sync(0xffffffffu, acc, off);
    if ((threadIdx.x & 31) == 0) sred[threadIdx.x >> 5] = acc;
    __syncthreads();
    if (threadIdx.x == 0) {
        float t = sred[0] + sred[1] + sred[2] + sred[3];
        g_rsum[bj] = 1.f / t;
    }
}

// ============================================================
// Kernel 3 (HBM-bound): one block per (b,i) row.
// Streams L_real/L_imag exactly once (268 MB) -> g_row (interleaved).
// ============================================================
__global__ void __launch_bounds__(256) k3_main(
    const float* __restrict__ Lr, const float* __restrict__ Li,
    const float* __restrict__ par, const float* __restrict__ pai)
{
    int bi = blockIdx.x;          // b*N + i
    int b  = bi >> 10;
    int i  = bi & 1023;
    int tid = threadIdx.x;
    int j0 = tid * 4;

    float sRi = g_sRi[bi], sIi = g_sIi[bi];
    float a_r = par[0], a_i = pai[0];

    const int bj0 = (b << 10) + j0;
    float4 sRj4 = *(const float4*)(g_sRj + bj0);
    float4 sIj4 = *(const float4*)(g_sIj + bj0);
    float4 rs4  = *(const float4*)(g_rsum + bj0);
    float sRjv[4] = {sRj4.x, sRj4.y, sRj4.z, sRj4.w};
    float sIjv[4] = {sIj4.x, sIj4.y, sIj4.z, sIj4.w};
    float rsv [4] = {rs4.x,  rs4.y,  rs4.z,  rs4.w };

    float ar[4], ai[4];
#pragma unroll
    for (int k = 0; k < 4; k++) {
        float sr = sRi + sRjv[k];
        float si = sIi + sIjv[k];
        float pr = sr >= 0.f ? sr : a_r * sr;
        float pi = si >= 0.f ? si : a_i * si;
        float r2 = pr * pr + pi * pi;
        float inv = rsqrtf(fmaxf(r2, 1e-30f));
        float mag = r2 * inv;
        float e = __expf(mag);
        float sc = e * inv * rsv[k];
        ar[k] = sc * pr;
        ai[k] = sc * pi;
    }

    float accR[4], accI[4];
#pragma unroll
    for (int m = 0; m < 4; m++) { accR[m] = 0.f; accI[m] = 0.f; }

#pragma unroll
    for (int m = 0; m < 4; m++) {
        size_t base = ((size_t)((b * 4 + m) * N_ + i)) * N_ + j0;
        float4 lr = *(const float4*)(Lr + base);
        float4 li = *(const float4*)(Li + base);
        accR[m] += lr.x * ar[0] - li.x * ai[0];
        accR[m] += lr.y * ar[1] - li.y * ai[1];
        accR[m] += lr.z * ar[2] - li.z * ai[2];
        accR[m] += lr.w * ar[3] - li.w * ai[3];
        accI[m] += lr.x * ai[0] + li.x * ar[0];
        accI[m] += lr.y * ai[1] + li.y * ar[1];
        accI[m] += lr.z * ai[2] + li.z * ar[2];
        accI[m] += lr.w * ai[3] + li.w * ar[3];
    }

    __shared__ float sred[8][8];   // [warp][q]
#pragma unroll
    for (int q = 0; q < 8; q++) {
        float x = (q < 4) ? accR[q] : accI[q - 4];
#pragma unroll
        for (int off = 16; off; off >>= 1) x += __shfl_xor_sync(0xffffffffu, x, off);
        if ((tid & 31) == 0) sred[tid >> 5][q] = x;
    }
    __syncthreads();
    if (tid < 8) {
        float x = 0.f;
#pragma unroll
        for (int w = 0; w < 8; w++) x += sred[w][tid];
        g_row[(bi << 3) + tid] = x;    // [bn][0..3]=R, [4..7]=I
    }
}

// ============================================================
// Kernel 4: final einsums with packed f32x2 FFMA2 inner loop.
// Structure = R6 (JT=2, phased X double-buffer, 48 KB static smem,
// 128 thr, grid 4 oq x 128 jg = 512), but the inner product runs on
// fma.rn.f32x2 (halves FFMA instruction count) with w loaded via
// ld.shared.v2.b64 straight into f32x2 register pairs.
// ============================================================
#define XSW(j, q) (((j) << 2) | ((q) ^ ((j) & 3) ^ (((j) >> 2) & 3)))

#define FFMA2(acc, a, b) \
    asm("fma.rn.f32x2 %0, %1, %2, %0;" : "+l"(acc) : "l"(a), "l"(b))

#define PACK2(d, s) \
    asm("mov.b64 %0, {%1, %1};" : "=l"(d) : "f"(s))

#define LDS_V2B64(lo, hi, addr) \
    asm("ld.shared.v2.b64 {%0, %1}, [%2];" : "=l"(lo), "=l"(hi) : "r"(addr))

__global__ void __launch_bounds__(128, 4) k4_out(
    const float* __restrict__ Xr, const float* __restrict__ Xi,
    const float4* __restrict__ wr4, const float4* __restrict__ wi4,
    float* __restrict__ out)
{
    __shared__ float4 wr_s[KM * C_ * 4];     // (m*64+c)*4+og : 16 KB
    __shared__ float4 wi_s[KM * C_ * 4];     // 16 KB
    __shared__ float4 x_s[2][2][256];        // [buf][ri][XSW(j,q)] : 16 KB

    const int tid = threadIdx.x;
    const int og  = tid & 3;
    const int jl  = tid >> 2;                // 0..31
    const int bx  = blockIdx.x;
    const int jg  = bx & 127;
    const int oq  = bx >> 7;                 // 0..3
    const int jbase = jg * 64;

    const float4* XrG = (const float4*)Xr + (size_t)jbase * 16;
    const float4* XiG = (const float4*)Xi + (size_t)jbase * 16;

    // ---- w slice load (resident) ----
#pragma unroll
    for (int r = 0; r < 8; r++) {
        int e  = r * 128 + tid;              // 0..1023
        int mc = e >> 2, o2 = e & 3;
        wr_s[e] = wr4[mc * 16 + oq * 4 + o2];
        wi_s[e] = wi4[mc * 16 + oq * 4 + o2];
    }
    // ---- X phase 0 load ----
#pragma unroll
    for (int r = 0; r < 2; r++) {
        int e = r * 128 + tid;               // 0..255
        int j = e >> 2, q = e & 3;
        int si = XSW(j, q);
        x_s[0][0][si] = XrG[j * 16 + q];
        x_s[0][1][si] = XiG[j * 16 + q];
    }
    __syncthreads();

    // f32x2 accumulators: [m][pair], pair 0 = o{0,1}, pair 1 = o{2,3} of this thread's f4
    uint64_t PR0[4][2], PI0[4][2], PR1[4][2], PI1[4][2];
#pragma unroll
    for (int m = 0; m < 4; m++) {
        PR0[m][0] = PR0[m][1] = 0ull;  PI0[m][0] = PI0[m][1] = 0ull;
        PR1[m][0] = PR1[m][1] = 0ull;  PI1[m][0] = PI1[m][1] = 0ull;
    }

    const uint32_t wb_r = (uint32_t)__cvta_generic_to_shared(wr_s) + og * 16;
    const uint32_t wb_i = (uint32_t)__cvta_generic_to_shared(wi_s) + og * 16;

    const int j0 = jl, j1 = jl + 32;

#pragma unroll
    for (int p = 0; p < 4; p++) {
        int buf = p & 1;
        if (p < 3) {
            int nb = buf ^ 1;
#pragma unroll
            for (int r = 0; r < 2; r++) {
                int e = r * 128 + tid;
                int j = e >> 2, q = e & 3;
                int si = XSW(j, q);
                x_s[nb][0][si] = XrG[j * 16 + (p + 1) * 4 + q];
                x_s[nb][1][si] = XiG[j * 16 + (p + 1) * 4 + q];
            }
        }
#pragma unroll
        for (int q = 0; q < 4; q++) {
            float4 xr0 = x_s[buf][0][XSW(j0, q)];
            float4 xi0 = x_s[buf][1][XSW(j0, q)];
            float4 xr1 = x_s[buf][0][XSW(j1, q)];
            float4 xi1 = x_s[buf][1][XSW(j1, q)];
            const float* fxr0 = (const float*)&xr0;
            const float* fxi0 = (const float*)&xi0;
            const float* fxr1 = (const float*)&xr1;
            const float* fxi1 = (const float*)&xi1;
#pragma unroll
            for (int ci = 0; ci < 4; ci++) {
                const int c = p * 16 + q * 4 + ci;
                uint64_t a0p, b0p, a1p, b1p;
                PACK2(a0p, fxr0[ci]);
                PACK2(b0p, fxi0[ci]);
                PACK2(a1p, fxr1[ci]);
                PACK2(b1p, fxi1[ci]);
#pragma unroll
                for (int m = 0; m < 4; m++) {
                    const uint32_t off = (uint32_t)(((m << 6) + c) << 6);
                    uint64_t w0, w1, v0, v1;
                    LDS_V2B64(w0, w1, wb_r + off);
                    LDS_V2B64(v0, v1, wb_i + off);
                    FFMA2(PR0[m][0], a0p, w0);  FFMA2(PR0[m][1], a0p, w1);
                    FFMA2(PI0[m][0], b0p, v0);  FFMA2(PI0[m][1], b0p, v1);
                    FFMA2(PR1[m][0], a1p, w0);  FFMA2(PR1[m][1], a1p, w1);
                    FFMA2(PI1[m][0], b1p, v0);  FFMA2(PI1[m][1], b1p, v1);
                }
            }
        }
        __syncthreads();
    }

    // ---- combine over m with row vectors and store ----
#pragma unroll
    for (int jt = 0; jt < 2; jt++) {
        int jj = jbase + jl + jt * 32;       // global bn index
        const float4* row4 = (const float4*)g_row;
        float4 rR = row4[jj * 2];
        float4 rI = row4[jj * 2 + 1];
        const float* aR = (const float*)&rR;
        const float* aI = (const float*)&rI;

        float4 re = make_float4(0.f,0.f,0.f,0.f);
        float4 im = make_float4(0.f,0.f,0.f,0.f);
#pragma unroll
        for (int m = 0; m < 4; m++) {
            float a  = aR[m];
            float bi = aI[m];
            float2 pr0 = jt ? *(float2*)&PR1[m][0] : *(float2*)&PR0[m][0];
            float2 pr1 = jt ? *(float2*)&PR1[m][1] : *(float2*)&PR0[m][1];
            float2 pi0 = jt ? *(float2*)&PI1[m][0] : *(float2*)&PI0[m][0];
            float2 pi1 = jt ? *(float2*)&PI1[m][1] : *(float2*)&PI0[m][1];
            re.x += a * pr0.x - bi * pi0.x;  re.y += a * pr0.y - bi * pi0.y;
            re.z += a * pr1.x - bi * pi1.x;  re.w += a * pr1.y - bi * pi1.y;
            im.x += bi * pr0.x + a * pi0.x;  im.y += bi * pr0.y + a * pi0.y;
            im.z += bi * pr1.x + a * pi1.x;  im.w += bi * pr1.y + a * pi1.y;
        }
        ((float4*)out)[jj * 16 + oq * 4 + og] = re;                 // real
        ((float4*)out)[BN * 16 + jj * 16 + oq * 4 + og] = im;       // imag
    }
}

// ============================================================
extern "C" void kernel_launch(void* const* d_in, const int* in_sizes, int n_in,
                              void* d_out, int out_size)
{
    const float* Xr  = (const float*)d_in[0];
    const float* Xi  = (const float*)d_in[1];
    const float* Lr  = (const float*)d_in[2];
    const float* Li  = (const float*)d_in[3];
    const float* wr  = (const float*)d_in[4];
    const float* wi  = (const float*)d_in[5];
    const float* awr = (const float*)d_in[6];
    const float* awi = (const float*)d_in[7];
    const float* abr = (const float*)d_in[8];
    const float* abi = (const float*)d_in[9];
    const float* par = (const float*)d_in[10];
    const float* pai = (const float*)d_in[11];
    float* out = (float*)d_out;

    k1_proj  <<<BN / 8, 256>>>(Xr, Xi, awr, awi, abr, abi);
    k2_sumexp<<<BN,     128>>>(par, pai);
    k3_main  <<<BN,     256>>>(Lr, Li, par, pai);
    k4_out   <<<4 * 128, 128>>>(Xr, Xi, (const float4*)wr, (const float4*)wi, out);
}